// round 9
// baseline (speedup 1.0000x reference)
#include <cuda_runtime.h>
#include <cuda_bf16.h>
#include <stdint.h>

// Problem constants
#define NN   100000
#define EE   1600000
#define FIN  128
#define HID  128
#define OUTD 256
#define SCAN_B 512

// -------- device scratch (static, no allocation) --------
__device__ float g_bufA[(size_t)NN * HID];   // GEMM output / agg input
__device__ float g_bufB[(size_t)NN * HID];   // agg output / next GEMM input
__device__ int   g_cnt[NN];                  // degree incl. self loop
__device__ int   g_inc[NN];                  // inclusive scan scratch
__device__ int   g_rowptr[NN];               // exclusive offsets
__device__ int   g_nxt[NN];                  // scatter cursors
__device__ int   g_col[EE + NN];             // CSR: src indices per dst row
__device__ float g_dinv[NN];                 // rsqrt(deg)
__device__ int   g_bsum[256];                // block sums for scan
__device__ float g_psum[HID];                // pooled sum
__device__ int   g_pmax[HID];                // pooled max (float bits, relu>=0)
__device__ int   g_is64;                     // 1 if edge_index is int64, 0 if int32

// ---------------- init: cnt=1 (self loop), zero pooled, sniff dtype ----------------
// int64 little-endian with values in [0,1e5): every odd 32-bit word == 0.
__global__ void init_kernel(const int* __restrict__ w) {
    int i = blockIdx.x * blockDim.x + threadIdx.x;
    if (i < NN) g_cnt[i] = 1;
    if (i < HID) { g_psum[i] = 0.0f; g_pmax[i] = 0; }
    if (i == 0) {
        int all0 = 1;
        for (int k = 0; k < 256; k++)
            if (w[2 * k + 1] != 0) { all0 = 0; break; }
        g_is64 = all0;
    }
}

__device__ __forceinline__ int edge_src(const int* w, int e, int is64) {
    return is64 ? w[2 * (size_t)e] : w[e];
}
__device__ __forceinline__ int edge_dst(const int* w, int e, int is64) {
    return is64 ? w[2 * ((size_t)EE + e)] : w[EE + e];
}

// ---------------- count in-degree over edges ----------------
__global__ void count_kernel(const int* __restrict__ w) {
    int is64 = g_is64;
    int stride = gridDim.x * blockDim.x;
    for (int e = blockIdx.x * blockDim.x + threadIdx.x; e < EE; e += stride) {
        int d = edge_dst(w, e, is64);
        atomicAdd(&g_cnt[d], 1);
    }
}

// ---------------- scan stage 1 ----------------
__global__ void scan1_kernel() {
    __shared__ int sh[SCAN_B];
    int tid = threadIdx.x;
    int i = blockIdx.x * SCAN_B + tid;
    int v = (i < NN) ? g_cnt[i] : 0;
    sh[tid] = v;
    __syncthreads();
#pragma unroll
    for (int off = 1; off < SCAN_B; off <<= 1) {
        int t = 0;
        if (tid >= off) t = sh[tid - off];
        __syncthreads();
        sh[tid] += t;
        __syncthreads();
    }
    if (i < NN) g_inc[i] = sh[tid];
    if (tid == SCAN_B - 1) g_bsum[blockIdx.x] = sh[tid];
}

// ---------------- scan stage 2 ----------------
__global__ void scan2_kernel(int nb) {
    __shared__ int sh[256];
    int t = threadIdx.x;
    sh[t] = (t < nb) ? g_bsum[t] : 0;
    __syncthreads();
#pragma unroll
    for (int off = 1; off < 256; off <<= 1) {
        int v = 0;
        if (t >= off) v = sh[t - off];
        __syncthreads();
        sh[t] += v;
        __syncthreads();
    }
    int excl = (t == 0) ? 0 : sh[t - 1];
    if (t < nb) g_bsum[t] = excl;
}

// ---------------- scan stage 3 ----------------
__global__ void scan3_kernel() {
    int i = blockIdx.x * blockDim.x + threadIdx.x;
    if (i >= NN) return;
    int c = g_cnt[i];
    int excl = g_inc[i] - c + g_bsum[i / SCAN_B];
    g_rowptr[i] = excl;
    g_nxt[i] = excl + 1;      // slot 0 holds the self loop
    g_col[excl] = i;
    g_dinv[i] = rsqrtf((float)c);
}

// ---------------- bucket scatter ----------------
__global__ void scatter_kernel(const int* __restrict__ w) {
    int is64 = g_is64;
    int stride = gridDim.x * blockDim.x;
    for (int e = blockIdx.x * blockDim.x + threadIdx.x; e < EE; e += stride) {
        int s = edge_src(w, e, is64);
        int d = edge_dst(w, e, is64);
        int pos = atomicAdd(&g_nxt[d], 1);
        g_col[pos] = s;
    }
}

// ---------------- dense GEMM: C[M,128] = A[M,128] @ W[128,128] ----------------
// BM=64, BN=128, BK=16; 256 threads = 32x8; each thread: 8 rows x 4 cols (float4)
__global__ __launch_bounds__(256) void gemm_kernel(
    const float* __restrict__ A, const float* __restrict__ W,
    float* __restrict__ C, int M)
{
    __shared__ float As[16][65];     // padded: [k][row]
    __shared__ float Bs[16][128];    // [k][col]
    const int tx = threadIdx.x & 31;   // col group
    const int ty = threadIdx.x >> 5;   // row group
    const int m0 = blockIdx.x * 64;

    float acc[8][4];
#pragma unroll
    for (int i = 0; i < 8; i++)
#pragma unroll
        for (int j = 0; j < 4; j++) acc[i][j] = 0.0f;

    const int arow = threadIdx.x >> 2;          // 0..63
    const int aq   = (threadIdx.x & 3) * 4;     // 0,4,8,12

#pragma unroll
    for (int k0 = 0; k0 < 128; k0 += 16) {
        float4 av = make_float4(0.f, 0.f, 0.f, 0.f);
        if (m0 + arow < M)
            av = *(const float4*)(A + (size_t)(m0 + arow) * 128 + k0 + aq);
        float4 bv0 = *(const float4*)(W + k0 * 128 + threadIdx.x * 4);
        float4 bv1 = *(const float4*)(W + k0 * 128 + 1024 + threadIdx.x * 4);
        __syncthreads();
        As[aq + 0][arow] = av.x;
        As[aq + 1][arow] = av.y;
        As[aq + 2][arow] = av.z;
        As[aq + 3][arow] = av.w;
        ((float4*)Bs)[threadIdx.x]       = bv0;
        ((float4*)Bs)[threadIdx.x + 256] = bv1;
        __syncthreads();
#pragma unroll
        for (int k = 0; k < 16; k++) {
            float4 b4 = *(const float4*)(&Bs[k][tx * 4]);
#pragma unroll
            for (int i = 0; i < 8; i++) {
                float a = As[k][ty * 8 + i];
                acc[i][0] = fmaf(a, b4.x, acc[i][0]);
                acc[i][1] = fmaf(a, b4.y, acc[i][1]);
                acc[i][2] = fmaf(a, b4.z, acc[i][2]);
                acc[i][3] = fmaf(a, b4.w, acc[i][3]);
            }
        }
    }
#pragma unroll
    for (int i = 0; i < 8; i++) {
        int row = m0 + ty * 8 + i;
        if (row < M)
            *(float4*)(C + (size_t)row * 128 + tx * 4) =
                make_float4(acc[i][0], acc[i][1], acc[i][2], acc[i][3]);
    }
}

// ---------------- aggregation: one warp per node, 4-way MLP unroll ----------------
// out[n,:] = relu( dinv[n] * sum_{s in row n} h[s,:]*dinv[s] + bias )
__global__ __launch_bounds__(256) void agg_kernel(
    const float* __restrict__ h, const float* __restrict__ bias,
    float* __restrict__ out)
{
    int node = (blockIdx.x * blockDim.x + threadIdx.x) >> 5;
    int lane = threadIdx.x & 31;
    if (node >= NN) return;
    int beg = g_rowptr[node];
    int e   = g_cnt[node];
    float4 acc0 = make_float4(0.f, 0.f, 0.f, 0.f);
    float4 acc1 = make_float4(0.f, 0.f, 0.f, 0.f);
    int i = 0;
    for (; i + 3 < e; i += 4) {
        int s[4];
        float d[4];
        float4 v[4];
#pragma unroll
        for (int j = 0; j < 4; j++) s[j] = g_col[beg + i + j];
#pragma unroll
        for (int j = 0; j < 4; j++) d[j] = __ldg(&g_dinv[s[j]]);
#pragma unroll
        for (int j = 0; j < 4; j++)
            v[j] = *(const float4*)(h + (size_t)s[j] * HID + lane * 4);
        acc0.x = fmaf(v[0].x, d[0], fmaf(v[1].x, d[1], acc0.x));
        acc0.y = fmaf(v[0].y, d[0], fmaf(v[1].y, d[1], acc0.y));
        acc0.z = fmaf(v[0].z, d[0], fmaf(v[1].z, d[1], acc0.z));
        acc0.w = fmaf(v[0].w, d[0], fmaf(v[1].w, d[1], acc0.w));
        acc1.x = fmaf(v[2].x, d[2], fmaf(v[3].x, d[3], acc1.x));
        acc1.y = fmaf(v[2].y, d[2], fmaf(v[3].y, d[3], acc1.y));
        acc1.z = fmaf(v[2].z, d[2], fmaf(v[3].z, d[3], acc1.z));
        acc1.w = fmaf(v[2].w, d[2], fmaf(v[3].w, d[3], acc1.w));
    }
    for (; i < e; i++) {
        int s0 = g_col[beg + i];
        float d0 = __ldg(&g_dinv[s0]);
        float4 v0 = *(const float4*)(h + (size_t)s0 * HID + lane * 4);
        acc0.x = fmaf(v0.x, d0, acc0.x);
        acc0.y = fmaf(v0.y, d0, acc0.y);
        acc0.z = fmaf(v0.z, d0, acc0.z);
        acc0.w = fmaf(v0.w, d0, acc0.w);
    }
    float dn = g_dinv[node];
    float4 b = *(const float4*)(bias + lane * 4);
    float4 o;
    o.x = fmaxf(fmaf(acc0.x + acc1.x, dn, b.x), 0.f);
    o.y = fmaxf(fmaf(acc0.y + acc1.y, dn, b.y), 0.f);
    o.z = fmaxf(fmaf(acc0.z + acc1.z, dn, b.z), 0.f);
    o.w = fmaxf(fmaf(acc0.w + acc1.w, dn, b.w), 0.f);
    *(float4*)(out + (size_t)node * HID + lane * 4) = o;
}

// ---------------- global mean+max pool over rows ----------------
__global__ __launch_bounds__(256) void pool_kernel(const float* __restrict__ x) {
    int lane = threadIdx.x & 31;
    int w = threadIdx.x >> 5;
    int warps_per_grid = gridDim.x * (blockDim.x >> 5);
    float4 s = make_float4(0.f, 0.f, 0.f, 0.f);
    float4 m = make_float4(0.f, 0.f, 0.f, 0.f);   // relu output >= 0
    for (int r = blockIdx.x * (blockDim.x >> 5) + w; r < NN; r += warps_per_grid) {
        float4 v = *(const float4*)(x + (size_t)r * HID + lane * 4);
        s.x += v.x; s.y += v.y; s.z += v.z; s.w += v.w;
        m.x = fmaxf(m.x, v.x); m.y = fmaxf(m.y, v.y);
        m.z = fmaxf(m.z, v.z); m.w = fmaxf(m.w, v.w);
    }
    __shared__ float4 ss[8][32];
    __shared__ float4 sm[8][32];
    ss[w][lane] = s;
    sm[w][lane] = m;
    __syncthreads();
    if (w == 0) {
#pragma unroll
        for (int i = 1; i < 8; i++) {
            float4 a = ss[i][lane], b = sm[i][lane];
            s.x += a.x; s.y += a.y; s.z += a.z; s.w += a.w;
            m.x = fmaxf(m.x, b.x); m.y = fmaxf(m.y, b.y);
            m.z = fmaxf(m.z, b.z); m.w = fmaxf(m.w, b.w);
        }
        atomicAdd(&g_psum[lane * 4 + 0], s.x);
        atomicAdd(&g_psum[lane * 4 + 1], s.y);
        atomicAdd(&g_psum[lane * 4 + 2], s.z);
        atomicAdd(&g_psum[lane * 4 + 3], s.w);
        atomicMax(&g_pmax[lane * 4 + 0], __float_as_int(m.x));
        atomicMax(&g_pmax[lane * 4 + 1], __float_as_int(m.y));
        atomicMax(&g_pmax[lane * 4 + 2], __float_as_int(m.z));
        atomicMax(&g_pmax[lane * 4 + 3], __float_as_int(m.w));
    }
}

// ---------------- final FC ----------------
__global__ void fc_kernel(
    const float* __restrict__ fcW, const float* __restrict__ fcb,
    float* __restrict__ out)
{
    __shared__ float p[2 * HID];
    int t = threadIdx.x;
    if (t < HID)      p[t] = g_psum[t] * (1.0f / (float)NN);
    else              p[t] = __int_as_float(g_pmax[t - HID]);
    __syncthreads();
    float acc = fcb[t];
#pragma unroll 8
    for (int i = 0; i < 2 * HID; i++)
        acc = fmaf(p[i], fcW[i * OUTD + t], acc);
    out[t] = acc;
}

// ---------------- launch ----------------
extern "C" void kernel_launch(void* const* d_in, const int* in_sizes, int n_in,
                              void* d_out, int out_size)
{
    const float* x    = (const float*)d_in[0];
    const int*   eiw  = (const int*)d_in[1];     // 32-bit word view of edge_index
    const float* W1   = (const float*)d_in[2];
    const float* b1   = (const float*)d_in[3];
    const float* W2   = (const float*)d_in[4];
    const float* b2   = (const float*)d_in[5];
    const float* fcW  = (const float*)d_in[6];
    const float* fcb  = (const float*)d_in[7];
    float*       out  = (float*)d_out;

    float* bufA; cudaGetSymbolAddress((void**)&bufA, g_bufA);
    float* bufB; cudaGetSymbolAddress((void**)&bufB, g_bufB);

    const int nScanBlocks = (NN + SCAN_B - 1) / SCAN_B;   // 196
    const int nAggBlocks  = (NN * 32 + 255) / 256;        // 12500

    // CSR build (serial, single stream — fork regressed in R6)
    init_kernel<<<(NN + 255) / 256, 256>>>(eiw);
    count_kernel<<<1184, 256>>>(eiw);
    scan1_kernel<<<nScanBlocks, SCAN_B>>>();
    scan2_kernel<<<1, 256>>>(nScanBlocks);
    scan3_kernel<<<(NN + 255) / 256, 256>>>();
    scatter_kernel<<<1184, 256>>>(eiw);

    // layer 1
    gemm_kernel<<<(NN + 63) / 64, 256>>>(x, W1, bufA, NN);
    agg_kernel<<<nAggBlocks, 256>>>(bufA, b1, bufB);
    // layer 2
    gemm_kernel<<<(NN + 63) / 64, 256>>>(bufB, W2, bufA, NN);
    agg_kernel<<<nAggBlocks, 256>>>(bufA, b2, bufB);

    // pool + fc
    pool_kernel<<<592, 256>>>(bufB);
    fc_kernel<<<1, 2 * HID>>>(fcW, fcb, out);
}

// round 10
// speedup vs baseline: 1.2129x; 1.2129x over previous
#include <cuda_runtime.h>
#include <cuda_bf16.h>
#include <stdint.h>

// Problem constants
#define NN   100000
#define EE   1600000
#define FIN  128
#define HID  128
#define OUTD 256
#define SCAN_B 512

// -------- device scratch (static, no allocation) --------
__device__ __nv_bfloat16 g_h[(size_t)NN * HID];  // GEMM output in bf16 (agg gather operand)
__device__ float g_bufB[(size_t)NN * HID];       // agg output / next GEMM input (fp32)
__device__ int   g_cnt[NN];                      // degree incl. self loop
__device__ int   g_inc[NN];                      // inclusive scan scratch
__device__ int   g_rowptr[NN];                   // exclusive offsets
__device__ int   g_nxt[NN];                      // scatter cursors
__device__ int   g_col[EE + NN];                 // CSR: src indices per dst row
__device__ float g_dinv[NN];                     // rsqrt(deg)
__device__ int   g_bsum[256];                    // block sums for scan
__device__ float g_psum[HID];                    // pooled sum
__device__ int   g_pmax[HID];                    // pooled max (float bits, relu>=0)
__device__ int   g_is64;                         // 1 if edge_index is int64, 0 if int32

// ---------------- init: cnt=1 (self loop), zero pooled, sniff dtype ----------------
// int64 little-endian with values in [0,1e5): every odd 32-bit word == 0.
__global__ void init_kernel(const int* __restrict__ w) {
    int i = blockIdx.x * blockDim.x + threadIdx.x;
    if (i < NN) g_cnt[i] = 1;
    if (i < HID) { g_psum[i] = 0.0f; g_pmax[i] = 0; }
    if (i == 0) {
        int all0 = 1;
        for (int k = 0; k < 256; k++)
            if (w[2 * k + 1] != 0) { all0 = 0; break; }
        g_is64 = all0;
    }
}

__device__ __forceinline__ int edge_src(const int* w, int e, int is64) {
    return is64 ? w[2 * (size_t)e] : w[e];
}
__device__ __forceinline__ int edge_dst(const int* w, int e, int is64) {
    return is64 ? w[2 * ((size_t)EE + e)] : w[EE + e];
}

// ---------------- count in-degree over edges ----------------
__global__ void count_kernel(const int* __restrict__ w) {
    int is64 = g_is64;
    int stride = gridDim.x * blockDim.x;
    for (int e = blockIdx.x * blockDim.x + threadIdx.x; e < EE; e += stride) {
        int d = edge_dst(w, e, is64);
        atomicAdd(&g_cnt[d], 1);
    }
}

// ---------------- scan stage 1 ----------------
__global__ void scan1_kernel() {
    __shared__ int sh[SCAN_B];
    int tid = threadIdx.x;
    int i = blockIdx.x * SCAN_B + tid;
    int v = (i < NN) ? g_cnt[i] : 0;
    sh[tid] = v;
    __syncthreads();
#pragma unroll
    for (int off = 1; off < SCAN_B; off <<= 1) {
        int t = 0;
        if (tid >= off) t = sh[tid - off];
        __syncthreads();
        sh[tid] += t;
        __syncthreads();
    }
    if (i < NN) g_inc[i] = sh[tid];
    if (tid == SCAN_B - 1) g_bsum[blockIdx.x] = sh[tid];
}

// ---------------- scan stage 2 ----------------
__global__ void scan2_kernel(int nb) {
    __shared__ int sh[256];
    int t = threadIdx.x;
    sh[t] = (t < nb) ? g_bsum[t] : 0;
    __syncthreads();
#pragma unroll
    for (int off = 1; off < 256; off <<= 1) {
        int v = 0;
        if (t >= off) v = sh[t - off];
        __syncthreads();
        sh[t] += v;
        __syncthreads();
    }
    int excl = (t == 0) ? 0 : sh[t - 1];
    if (t < nb) g_bsum[t] = excl;
}

// ---------------- scan stage 3 ----------------
__global__ void scan3_kernel() {
    int i = blockIdx.x * blockDim.x + threadIdx.x;
    if (i >= NN) return;
    int c = g_cnt[i];
    int excl = g_inc[i] - c + g_bsum[i / SCAN_B];
    g_rowptr[i] = excl;
    g_nxt[i] = excl + 1;      // slot 0 holds the self loop
    g_col[excl] = i;
    g_dinv[i] = rsqrtf((float)c);
}

// ---------------- bucket scatter ----------------
__global__ void scatter_kernel(const int* __restrict__ w) {
    int is64 = g_is64;
    int stride = gridDim.x * blockDim.x;
    for (int e = blockIdx.x * blockDim.x + threadIdx.x; e < EE; e += stride) {
        int s = edge_src(w, e, is64);
        int d = edge_dst(w, e, is64);
        int pos = atomicAdd(&g_nxt[d], 1);
        g_col[pos] = s;
    }
}

// ---------------- dense GEMM: C_bf16[M,128] = A[M,128] @ W[128,128] ----------------
// BM=64, BN=128, BK=16; 256 threads = 32x8; each thread: 8 rows x 4 cols
__global__ __launch_bounds__(256) void gemm_kernel(
    const float* __restrict__ A, const float* __restrict__ W,
    __nv_bfloat16* __restrict__ C, int M)
{
    __shared__ float As[16][65];     // padded: [k][row]
    __shared__ float Bs[16][128];    // [k][col]
    const int tx = threadIdx.x & 31;   // col group
    const int ty = threadIdx.x >> 5;   // row group
    const int m0 = blockIdx.x * 64;

    float acc[8][4];
#pragma unroll
    for (int i = 0; i < 8; i++)
#pragma unroll
        for (int j = 0; j < 4; j++) acc[i][j] = 0.0f;

    const int arow = threadIdx.x >> 2;          // 0..63
    const int aq   = (threadIdx.x & 3) * 4;     // 0,4,8,12

#pragma unroll
    for (int k0 = 0; k0 < 128; k0 += 16) {
        float4 av = make_float4(0.f, 0.f, 0.f, 0.f);
        if (m0 + arow < M)
            av = *(const float4*)(A + (size_t)(m0 + arow) * 128 + k0 + aq);
        float4 bv0 = *(const float4*)(W + k0 * 128 + threadIdx.x * 4);
        float4 bv1 = *(const float4*)(W + k0 * 128 + 1024 + threadIdx.x * 4);
        __syncthreads();
        As[aq + 0][arow] = av.x;
        As[aq + 1][arow] = av.y;
        As[aq + 2][arow] = av.z;
        As[aq + 3][arow] = av.w;
        ((float4*)Bs)[threadIdx.x]       = bv0;
        ((float4*)Bs)[threadIdx.x + 256] = bv1;
        __syncthreads();
#pragma unroll
        for (int k = 0; k < 16; k++) {
            float4 b4 = *(const float4*)(&Bs[k][tx * 4]);
#pragma unroll
            for (int i = 0; i < 8; i++) {
                float a = As[k][ty * 8 + i];
                acc[i][0] = fmaf(a, b4.x, acc[i][0]);
                acc[i][1] = fmaf(a, b4.y, acc[i][1]);
                acc[i][2] = fmaf(a, b4.z, acc[i][2]);
                acc[i][3] = fmaf(a, b4.w, acc[i][3]);
            }
        }
    }
#pragma unroll
    for (int i = 0; i < 8; i++) {
        int row = m0 + ty * 8 + i;
        if (row < M) {
            __nv_bfloat162 p0 = __floats2bfloat162_rn(acc[i][0], acc[i][1]);
            __nv_bfloat162 p1 = __floats2bfloat162_rn(acc[i][2], acc[i][3]);
            uint2 u;
            u.x = *(unsigned int*)&p0;
            u.y = *(unsigned int*)&p1;
            *(uint2*)(C + (size_t)row * 128 + tx * 4) = u;
        }
    }
}

// ---------------- aggregation: one warp per node, bf16 gather (8B per lane) ----------------
// out[n,:] = relu( dinv[n] * sum_{s in row n} h[s,:]*dinv[s] + bias )
__device__ __forceinline__ float4 bf16row_to_f4(uint2 u) {
    __nv_bfloat162 p0 = *(__nv_bfloat162*)&u.x;
    __nv_bfloat162 p1 = *(__nv_bfloat162*)&u.y;
    float2 f0 = __bfloat1622float2(p0);
    float2 f1 = __bfloat1622float2(p1);
    return make_float4(f0.x, f0.y, f1.x, f1.y);
}

__global__ __launch_bounds__(256) void agg_kernel(
    const __nv_bfloat16* __restrict__ h, const float* __restrict__ bias,
    float* __restrict__ out)
{
    int node = (blockIdx.x * blockDim.x + threadIdx.x) >> 5;
    int lane = threadIdx.x & 31;
    if (node >= NN) return;
    int beg = g_rowptr[node];
    int e   = g_cnt[node];
    float4 acc = make_float4(0.f, 0.f, 0.f, 0.f);
    int i = 0;
    for (; i + 1 < e; i += 2) {
        int s0 = g_col[beg + i];
        int s1 = g_col[beg + i + 1];
        float d0 = __ldg(&g_dinv[s0]);
        float d1 = __ldg(&g_dinv[s1]);
        uint2 u0 = *(const uint2*)(h + (size_t)s0 * HID + lane * 4);
        uint2 u1 = *(const uint2*)(h + (size_t)s1 * HID + lane * 4);
        float4 v0 = bf16row_to_f4(u0);
        float4 v1 = bf16row_to_f4(u1);
        acc.x = fmaf(v0.x, d0, fmaf(v1.x, d1, acc.x));
        acc.y = fmaf(v0.y, d0, fmaf(v1.y, d1, acc.y));
        acc.z = fmaf(v0.z, d0, fmaf(v1.z, d1, acc.z));
        acc.w = fmaf(v0.w, d0, fmaf(v1.w, d1, acc.w));
    }
    if (i < e) {
        int s0 = g_col[beg + i];
        float d0 = __ldg(&g_dinv[s0]);
        float4 v0 = bf16row_to_f4(*(const uint2*)(h + (size_t)s0 * HID + lane * 4));
        acc.x = fmaf(v0.x, d0, acc.x);
        acc.y = fmaf(v0.y, d0, acc.y);
        acc.z = fmaf(v0.z, d0, acc.z);
        acc.w = fmaf(v0.w, d0, acc.w);
    }
    float dn = g_dinv[node];
    float4 b = *(const float4*)(bias + lane * 4);
    float4 o;
    o.x = fmaxf(fmaf(acc.x, dn, b.x), 0.f);
    o.y = fmaxf(fmaf(acc.y, dn, b.y), 0.f);
    o.z = fmaxf(fmaf(acc.z, dn, b.z), 0.f);
    o.w = fmaxf(fmaf(acc.w, dn, b.w), 0.f);
    *(float4*)(out + (size_t)node * HID + lane * 4) = o;
}

// ---------------- global mean+max pool over rows ----------------
__global__ __launch_bounds__(256) void pool_kernel(const float* __restrict__ x) {
    int lane = threadIdx.x & 31;
    int w = threadIdx.x >> 5;
    int warps_per_grid = gridDim.x * (blockDim.x >> 5);
    float4 s = make_float4(0.f, 0.f, 0.f, 0.f);
    float4 m = make_float4(0.f, 0.f, 0.f, 0.f);   // relu output >= 0
    for (int r = blockIdx.x * (blockDim.x >> 5) + w; r < NN; r += warps_per_grid) {
        float4 v = *(const float4*)(x + (size_t)r * HID + lane * 4);
        s.x += v.x; s.y += v.y; s.z += v.z; s.w += v.w;
        m.x = fmaxf(m.x, v.x); m.y = fmaxf(m.y, v.y);
        m.z = fmaxf(m.z, v.z); m.w = fmaxf(m.w, v.w);
    }
    __shared__ float4 ss[8][32];
    __shared__ float4 sm[8][32];
    ss[w][lane] = s;
    sm[w][lane] = m;
    __syncthreads();
    if (w == 0) {
#pragma unroll
        for (int i = 1; i < 8; i++) {
            float4 a = ss[i][lane], b = sm[i][lane];
            s.x += a.x; s.y += a.y; s.z += a.z; s.w += a.w;
            m.x = fmaxf(m.x, b.x); m.y = fmaxf(m.y, b.y);
            m.z = fmaxf(m.z, b.z); m.w = fmaxf(m.w, b.w);
        }
        atomicAdd(&g_psum[lane * 4 + 0], s.x);
        atomicAdd(&g_psum[lane * 4 + 1], s.y);
        atomicAdd(&g_psum[lane * 4 + 2], s.z);
        atomicAdd(&g_psum[lane * 4 + 3], s.w);
        atomicMax(&g_pmax[lane * 4 + 0], __float_as_int(m.x));
        atomicMax(&g_pmax[lane * 4 + 1], __float_as_int(m.y));
        atomicMax(&g_pmax[lane * 4 + 2], __float_as_int(m.z));
        atomicMax(&g_pmax[lane * 4 + 3], __float_as_int(m.w));
    }
}

// ---------------- final FC ----------------
__global__ void fc_kernel(
    const float* __restrict__ fcW, const float* __restrict__ fcb,
    float* __restrict__ out)
{
    __shared__ float p[2 * HID];
    int t = threadIdx.x;
    if (t < HID)      p[t] = g_psum[t] * (1.0f / (float)NN);
    else              p[t] = __int_as_float(g_pmax[t - HID]);
    __syncthreads();
    float acc = fcb[t];
#pragma unroll 8
    for (int i = 0; i < 2 * HID; i++)
        acc = fmaf(p[i], fcW[i * OUTD + t], acc);
    out[t] = acc;
}

// ---------------- launch ----------------
extern "C" void kernel_launch(void* const* d_in, const int* in_sizes, int n_in,
                              void* d_out, int out_size)
{
    const float* x    = (const float*)d_in[0];
    const int*   eiw  = (const int*)d_in[1];     // 32-bit word view of edge_index
    const float* W1   = (const float*)d_in[2];
    const float* b1   = (const float*)d_in[3];
    const float* W2   = (const float*)d_in[4];
    const float* b2   = (const float*)d_in[5];
    const float* fcW  = (const float*)d_in[6];
    const float* fcb  = (const float*)d_in[7];
    float*       out  = (float*)d_out;

    __nv_bfloat16* hbuf; cudaGetSymbolAddress((void**)&hbuf, g_h);
    float*         bufB; cudaGetSymbolAddress((void**)&bufB, g_bufB);

    const int nScanBlocks = (NN + SCAN_B - 1) / SCAN_B;   // 196
    const int nAggBlocks  = (NN * 32 + 255) / 256;        // 12500

    // CSR build (serial, single stream)
    init_kernel<<<(NN + 255) / 256, 256>>>(eiw);
    count_kernel<<<1184, 256>>>(eiw);
    scan1_kernel<<<nScanBlocks, SCAN_B>>>();
    scan2_kernel<<<1, 256>>>(nScanBlocks);
    scan3_kernel<<<(NN + 255) / 256, 256>>>();
    scatter_kernel<<<1184, 256>>>(eiw);

    // layer 1
    gemm_kernel<<<(NN + 63) / 64, 256>>>(x, W1, hbuf, NN);
    agg_kernel<<<nAggBlocks, 256>>>(hbuf, b1, bufB);
    // layer 2
    gemm_kernel<<<(NN + 63) / 64, 256>>>(bufB, W2, hbuf, NN);
    agg_kernel<<<nAggBlocks, 256>>>(hbuf, b2, bufB);

    // pool + fc
    pool_kernel<<<592, 256>>>(bufB);
    fc_kernel<<<1, 2 * HID>>>(fcW, fcb, out);
}

// round 12
// speedup vs baseline: 1.2490x; 1.0298x over previous
#include <cuda_runtime.h>
#include <cuda_bf16.h>
#include <stdint.h>

// Problem constants
#define NN   100000
#define EE   1600000
#define FIN  128
#define HID  128
#define OUTD 256
#define SCAN_B 512

// -------- device scratch (static, no allocation) --------
__device__ __nv_bfloat16 g_h[(size_t)NN * HID];  // GEMM output in bf16 (agg gather operand)
__device__ float g_bufB[(size_t)NN * HID];       // agg output / next GEMM input (fp32)
__device__ int   g_cnt[NN];                      // degree incl. self loop
__device__ int   g_inc[NN];                      // inclusive scan scratch
__device__ int   g_rowptr[NN];                   // exclusive offsets
__device__ int   g_nxt[NN];                      // scatter cursors
__device__ int   g_col[EE + NN];                 // CSR: src indices per dst row
__device__ float g_dinv[NN];                     // rsqrt(deg)
__device__ int   g_bsum[256];                    // block sums for scan
__device__ float g_psum[HID];                    // pooled sum
__device__ int   g_pmax[HID];                    // pooled max (float bits, relu>=0)
__device__ int   g_is64;                         // 1 if edge_index is int64, 0 if int32

// ---------------- init: cnt=1 (self loop), zero pooled, sniff dtype ----------------
// int64 little-endian with values in [0,1e5): every odd 32-bit word == 0.
__global__ void init_kernel(const int* __restrict__ w) {
    int i = blockIdx.x * blockDim.x + threadIdx.x;
    if (i < NN) g_cnt[i] = 1;
    if (i < HID) { g_psum[i] = 0.0f; g_pmax[i] = 0; }
    if (i == 0) {
        int all0 = 1;
        for (int k = 0; k < 256; k++)
            if (w[2 * k + 1] != 0) { all0 = 0; break; }
        g_is64 = all0;
    }
}

__device__ __forceinline__ int edge_src(const int* w, int e, int is64) {
    return is64 ? w[2 * (size_t)e] : w[e];
}
__device__ __forceinline__ int edge_dst(const int* w, int e, int is64) {
    return is64 ? w[2 * ((size_t)EE + e)] : w[EE + e];
}

// ---------------- count in-degree over edges ----------------
__global__ void count_kernel(const int* __restrict__ w) {
    int is64 = g_is64;
    int stride = gridDim.x * blockDim.x;
    for (int e = blockIdx.x * blockDim.x + threadIdx.x; e < EE; e += stride) {
        int d = edge_dst(w, e, is64);
        atomicAdd(&g_cnt[d], 1);
    }
}

// ---------------- scan stage 1 ----------------
__global__ void scan1_kernel() {
    __shared__ int sh[SCAN_B];
    int tid = threadIdx.x;
    int i = blockIdx.x * SCAN_B + tid;
    int v = (i < NN) ? g_cnt[i] : 0;
    sh[tid] = v;
    __syncthreads();
#pragma unroll
    for (int off = 1; off < SCAN_B; off <<= 1) {
        int t = 0;
        if (tid >= off) t = sh[tid - off];
        __syncthreads();
        sh[tid] += t;
        __syncthreads();
    }
    if (i < NN) g_inc[i] = sh[tid];
    if (tid == SCAN_B - 1) g_bsum[blockIdx.x] = sh[tid];
}

// ---------------- scan stage 2 ----------------
__global__ void scan2_kernel(int nb) {
    __shared__ int sh[256];
    int t = threadIdx.x;
    sh[t] = (t < nb) ? g_bsum[t] : 0;
    __syncthreads();
#pragma unroll
    for (int off = 1; off < 256; off <<= 1) {
        int v = 0;
        if (t >= off) v = sh[t - off];
        __syncthreads();
        sh[t] += v;
        __syncthreads();
    }
    int excl = (t == 0) ? 0 : sh[t - 1];
    if (t < nb) g_bsum[t] = excl;
}

// ---------------- scan stage 3 ----------------
__global__ void scan3_kernel() {
    int i = blockIdx.x * blockDim.x + threadIdx.x;
    if (i >= NN) return;
    int c = g_cnt[i];
    int excl = g_inc[i] - c + g_bsum[i / SCAN_B];
    g_rowptr[i] = excl;
    g_nxt[i] = excl + 1;      // slot 0 holds the self loop
    g_col[excl] = i;
    g_dinv[i] = rsqrtf((float)c);
}

// ---------------- bucket scatter ----------------
__global__ void scatter_kernel(const int* __restrict__ w) {
    int is64 = g_is64;
    int stride = gridDim.x * blockDim.x;
    for (int e = blockIdx.x * blockDim.x + threadIdx.x; e < EE; e += stride) {
        int s = edge_src(w, e, is64);
        int d = edge_dst(w, e, is64);
        int pos = atomicAdd(&g_nxt[d], 1);
        g_col[pos] = s;
    }
}

// ---------------- dense GEMM: C_bf16[M,128] = A[M,128] @ W[128,128] ----------------
// BM=64, BN=128, BK=16; 256 threads = 32x8; each thread: 8 rows x 4 cols
__global__ __launch_bounds__(256) void gemm_kernel(
    const float* __restrict__ A, const float* __restrict__ W,
    __nv_bfloat16* __restrict__ C, int M)
{
    __shared__ float As[16][65];     // padded: [k][row]
    __shared__ float Bs[16][128];    // [k][col]
    const int tx = threadIdx.x & 31;   // col group
    const int ty = threadIdx.x >> 5;   // row group
    const int m0 = blockIdx.x * 64;

    float acc[8][4];
#pragma unroll
    for (int i = 0; i < 8; i++)
#pragma unroll
        for (int j = 0; j < 4; j++) acc[i][j] = 0.0f;

    const int arow = threadIdx.x >> 2;          // 0..63
    const int aq   = (threadIdx.x & 3) * 4;     // 0,4,8,12

#pragma unroll
    for (int k0 = 0; k0 < 128; k0 += 16) {
        float4 av = make_float4(0.f, 0.f, 0.f, 0.f);
        if (m0 + arow < M)
            av = *(const float4*)(A + (size_t)(m0 + arow) * 128 + k0 + aq);
        float4 bv0 = *(const float4*)(W + k0 * 128 + threadIdx.x * 4);
        float4 bv1 = *(const float4*)(W + k0 * 128 + 1024 + threadIdx.x * 4);
        __syncthreads();
        As[aq + 0][arow] = av.x;
        As[aq + 1][arow] = av.y;
        As[aq + 2][arow] = av.z;
        As[aq + 3][arow] = av.w;
        ((float4*)Bs)[threadIdx.x]       = bv0;
        ((float4*)Bs)[threadIdx.x + 256] = bv1;
        __syncthreads();
#pragma unroll
        for (int k = 0; k < 16; k++) {
            float4 b4 = *(const float4*)(&Bs[k][tx * 4]);
#pragma unroll
            for (int i = 0; i < 8; i++) {
                float a = As[k][ty * 8 + i];
                acc[i][0] = fmaf(a, b4.x, acc[i][0]);
                acc[i][1] = fmaf(a, b4.y, acc[i][1]);
                acc[i][2] = fmaf(a, b4.z, acc[i][2]);
                acc[i][3] = fmaf(a, b4.w, acc[i][3]);
            }
        }
    }
#pragma unroll
    for (int i = 0; i < 8; i++) {
        int row = m0 + ty * 8 + i;
        if (row < M) {
            __nv_bfloat162 p0 = __floats2bfloat162_rn(acc[i][0], acc[i][1]);
            __nv_bfloat162 p1 = __floats2bfloat162_rn(acc[i][2], acc[i][3]);
            uint2 u;
            u.x = *(unsigned int*)&p0;
            u.y = *(unsigned int*)&p1;
            *(uint2*)(C + (size_t)row * 128 + tx * 4) = u;
        }
    }
}

// ---------------- aggregation: one warp per node, bf16 gather (8B per lane) ----------------
// out[n,:] = relu( dinv[n] * sum_{s in row n} h[s,:]*dinv[s] + bias )
__device__ __forceinline__ float4 bf16row_to_f4(uint2 u) {
    __nv_bfloat162 p0 = *(__nv_bfloat162*)&u.x;
    __nv_bfloat162 p1 = *(__nv_bfloat162*)&u.y;
    float2 f0 = __bfloat1622float2(p0);
    float2 f1 = __bfloat1622float2(p1);
    return make_float4(f0.x, f0.y, f1.x, f1.y);
}

__global__ __launch_bounds__(256) void agg_kernel(
    const __nv_bfloat16* __restrict__ h, const float* __restrict__ bias,
    float* __restrict__ out)
{
    int node = (blockIdx.x * blockDim.x + threadIdx.x) >> 5;
    int lane = threadIdx.x & 31;
    if (node >= NN) return;
    int beg = g_rowptr[node];
    int e   = g_cnt[node];
    float4 acc = make_float4(0.f, 0.f, 0.f, 0.f);
    int i = 0;
    for (; i + 1 < e; i += 2) {
        int s0 = g_col[beg + i];
        int s1 = g_col[beg + i + 1];
        float d0 = __ldg(&g_dinv[s0]);
        float d1 = __ldg(&g_dinv[s1]);
        uint2 u0 = *(const uint2*)(h + (size_t)s0 * HID + lane * 4);
        uint2 u1 = *(const uint2*)(h + (size_t)s1 * HID + lane * 4);
        float4 v0 = bf16row_to_f4(u0);
        float4 v1 = bf16row_to_f4(u1);
        acc.x = fmaf(v0.x, d0, fmaf(v1.x, d1, acc.x));
        acc.y = fmaf(v0.y, d0, fmaf(v1.y, d1, acc.y));
        acc.z = fmaf(v0.z, d0, fmaf(v1.z, d1, acc.z));
        acc.w = fmaf(v0.w, d0, fmaf(v1.w, d1, acc.w));
    }
    if (i < e) {
        int s0 = g_col[beg + i];
        float d0 = __ldg(&g_dinv[s0]);
        float4 v0 = bf16row_to_f4(*(const uint2*)(h + (size_t)s0 * HID + lane * 4));
        acc.x = fmaf(v0.x, d0, acc.x);
        acc.y = fmaf(v0.y, d0, acc.y);
        acc.z = fmaf(v0.z, d0, acc.z);
        acc.w = fmaf(v0.w, d0, acc.w);
    }
    float dn = g_dinv[node];
    float4 b = *(const float4*)(bias + lane * 4);
    float4 o;
    o.x = fmaxf(fmaf(acc.x, dn, b.x), 0.f);
    o.y = fmaxf(fmaf(acc.y, dn, b.y), 0.f);
    o.z = fmaxf(fmaf(acc.z, dn, b.z), 0.f);
    o.w = fmaxf(fmaf(acc.w, dn, b.w), 0.f);
    *(float4*)(out + (size_t)node * HID + lane * 4) = o;
}

// ---------------- global mean+max pool over rows ----------------
__global__ __launch_bounds__(256) void pool_kernel(const float* __restrict__ x) {
    int lane = threadIdx.x & 31;
    int w = threadIdx.x >> 5;
    int warps_per_grid = gridDim.x * (blockDim.x >> 5);
    float4 s = make_float4(0.f, 0.f, 0.f, 0.f);
    float4 m = make_float4(0.f, 0.f, 0.f, 0.f);   // relu output >= 0
    for (int r = blockIdx.x * (blockDim.x >> 5) + w; r < NN; r += warps_per_grid) {
        float4 v = *(const float4*)(x + (size_t)r * HID + lane * 4);
        s.x += v.x; s.y += v.y; s.z += v.z; s.w += v.w;
        m.x = fmaxf(m.x, v.x); m.y = fmaxf(m.y, v.y);
        m.z = fmaxf(m.z, v.z); m.w = fmaxf(m.w, v.w);
    }
    __shared__ float4 ss[8][32];
    __shared__ float4 sm[8][32];
    ss[w][lane] = s;
    sm[w][lane] = m;
    __syncthreads();
    if (w == 0) {
#pragma unroll
        for (int i = 1; i < 8; i++) {
            float4 a = ss[i][lane], b = sm[i][lane];
            s.x += a.x; s.y += a.y; s.z += a.z; s.w += a.w;
            m.x = fmaxf(m.x, b.x); m.y = fmaxf(m.y, b.y);
            m.z = fmaxf(m.z, b.z); m.w = fmaxf(m.w, b.w);
        }
        atomicAdd(&g_psum[lane * 4 + 0], s.x);
        atomicAdd(&g_psum[lane * 4 + 1], s.y);
        atomicAdd(&g_psum[lane * 4 + 2], s.z);
        atomicAdd(&g_psum[lane * 4 + 3], s.w);
        atomicMax(&g_pmax[lane * 4 + 0], __float_as_int(m.x));
        atomicMax(&g_pmax[lane * 4 + 1], __float_as_int(m.y));
        atomicMax(&g_pmax[lane * 4 + 2], __float_as_int(m.z));
        atomicMax(&g_pmax[lane * 4 + 3], __float_as_int(m.w));
    }
}

// ---------------- final FC ----------------
__global__ void fc_kernel(
    const float* __restrict__ fcW, const float* __restrict__ fcb,
    float* __restrict__ out)
{
    __shared__ float p[2 * HID];
    int t = threadIdx.x;
    if (t < HID)      p[t] = g_psum[t] * (1.0f / (float)NN);
    else              p[t] = __int_as_float(g_pmax[t - HID]);
    __syncthreads();
    float acc = fcb[t];
#pragma unroll 8
    for (int i = 0; i < 2 * HID; i++)
        acc = fmaf(p[i], fcW[i * OUTD + t], acc);
    out[t] = acc;
}

// ---------------- launch ----------------
extern "C" void kernel_launch(void* const* d_in, const int* in_sizes, int n_in,
                              void* d_out, int out_size)
{
    const float* x    = (const float*)d_in[0];
    const int*   eiw  = (const int*)d_in[1];     // 32-bit word view of edge_index
    const float* W1   = (const float*)d_in[2];
    const float* b1   = (const float*)d_in[3];
    const float* W2   = (const float*)d_in[4];
    const float* b2   = (const float*)d_in[5];
    const float* fcW  = (const float*)d_in[6];
    const float* fcb  = (const float*)d_in[7];
    float*       out  = (float*)d_out;

    __nv_bfloat16* hbuf; cudaGetSymbolAddress((void**)&hbuf, g_h);
    float*         bufB; cudaGetSymbolAddress((void**)&bufB, g_bufB);

    // side stream + events for fork/join (created once; reused across graph capture)
    static cudaStream_t s1 = nullptr;
    static cudaEvent_t evFork = nullptr, evJoin = nullptr;
    if (s1 == nullptr) {
        cudaStreamCreateWithFlags(&s1, cudaStreamNonBlocking);
        cudaEventCreateWithFlags(&evFork, cudaEventDisableTiming);
        cudaEventCreateWithFlags(&evJoin, cudaEventDisableTiming);
    }

    const int nScanBlocks = (NN + SCAN_B - 1) / SCAN_B;   // 196
    const int nAggBlocks  = (NN * 32 + 255) / 256;        // 12500

    // ---- fork: GEMM1 (depends only on x,W1) runs concurrent with CSR build ----
    cudaEventRecord(evFork, 0);
    cudaStreamWaitEvent(s1, evFork, 0);
    gemm_kernel<<<(NN + 63) / 64, 256, 0, s1>>>(x, W1, hbuf, NN);
    cudaEventRecord(evJoin, s1);

    // ---- CSR build on main stream ----
    init_kernel<<<(NN + 255) / 256, 256>>>(eiw);
    count_kernel<<<1184, 256>>>(eiw);
    scan1_kernel<<<nScanBlocks, SCAN_B>>>();
    scan2_kernel<<<1, 256>>>(nScanBlocks);
    scan3_kernel<<<(NN + 255) / 256, 256>>>();
    scatter_kernel<<<1184, 256>>>(eiw);

    // ---- join: agg1 needs both CSR and GEMM1 output ----
    cudaStreamWaitEvent(0, evJoin, 0);

    // layer 1 aggregation
    agg_kernel<<<nAggBlocks, 256>>>(hbuf, b1, bufB);
    // layer 2
    gemm_kernel<<<(NN + 63) / 64, 256>>>(bufB, W2, hbuf, NN);
    agg_kernel<<<nAggBlocks, 256>>>(hbuf, b2, bufB);

    // pool + fc
    pool_kernel<<<592, 256>>>(bufB);
    fc_kernel<<<1, 2 * HID>>>(fcW, fcb, out);
}